// round 4
// baseline (speedup 1.0000x reference)
#include <cuda_runtime.h>
#include <cstdint>

#define B_   64
#define L_   1024
#define ENC_ 2048
#define DEC_ 512
#define ATT_ 512

// ---------------- scratch (no allocs allowed) ----------------
__device__ float g_att2[B_ * ATT_];            // att2 + b_enc + b_dec
__device__ float g_part[4 * B_ * L_];          // logit partials per N-chunk
__device__ float g_Wt[ATT_ * ENC_];            // W_enc^T (ATT, ENC), tf32-rounded
__device__ float g_ctxp[4 * B_ * ENC_];        // context partials (L-split)

// ============================================================
// Transpose W_enc (ENC,ATT) -> g_Wt (ATT,ENC), rounding to tf32 (rna)
// ============================================================
__global__ void k_transpose(const float* __restrict__ We) {
    __shared__ float t[32][33];
    const int k0 = blockIdx.x * 32, n0 = blockIdx.y * 32;
    const int tx = threadIdx.x, ty = threadIdx.y;  // (32, 8)
    #pragma unroll
    for (int j = 0; j < 4; j++) {
        float v = We[(size_t)(k0 + ty + j * 8) * ATT_ + n0 + tx];
        uint32_t r;
        asm("cvt.rna.tf32.f32 %0, %1;" : "=r"(r) : "f"(v));
        t[ty + j * 8][tx] = __uint_as_float(r);
    }
    __syncthreads();
    #pragma unroll
    for (int j = 0; j < 4; j++)
        g_Wt[(size_t)(n0 + ty + j * 8) * ENC_ + k0 + tx] = t[tx][ty + j * 8];
}

// ============================================================
// att2[b][a] = dec[b]·W_dec[:,a] + b_dec[a] + b_enc[a]
// ============================================================
__global__ void k_att2(const float* __restrict__ dec, const float* __restrict__ Wd,
                       const float* __restrict__ bd, const float* __restrict__ be) {
    __shared__ float s[DEC_];
    int b = blockIdx.x, a = threadIdx.x;
    for (int d = threadIdx.x; d < DEC_; d += blockDim.x) s[d] = dec[b * DEC_ + d];
    __syncthreads();
    float acc = bd[a] + be[a];
    #pragma unroll 8
    for (int d = 0; d < DEC_; d++) acc = fmaf(s[d], Wd[d * ATT_ + a], acc);
    g_att2[b * ATT_ + a] = acc;
}

// ============================================================
// Big GEMM via mma.sync tf32 + fused relu/dot epilogue
// CTA 128x128, BK=32, 3-stage cp.async ring, one sync per iter.
// 8 warps: warp tile 64x32. grid(4, 512), block(256), 2 CTAs/SM.
// ============================================================
#define BK       32
#define NITER    (ENC_ / BK)            // 64
#define A_STG    16384                  // 128 rows * 128B
#define B_STG    16384
#define STG      (A_STG + B_STG)        // 32768
#define NSTAGE   3
#define SMEM_DYN (NSTAGE * STG)         // 98304

#define CP_ASYNC16(dst, src) \
    asm volatile("cp.async.cg.shared.global [%0], [%1], 16;" :: "r"(dst), "l"(src) : "memory")

__device__ __forceinline__ uint32_t smem_u32(const void* p) {
    uint32_t a;
    asm("{ .reg .u64 t; cvta.to.shared.u64 t, %1; cvt.u32.u64 %0, t; }" : "=r"(a) : "l"(p));
    return a;
}

__device__ __forceinline__ void mma_tf32(float* d, const uint32_t* a, const uint32_t* b) {
    asm volatile(
        "mma.sync.aligned.m16n8k8.row.col.f32.tf32.tf32.f32 "
        "{%0,%1,%2,%3}, {%4,%5,%6,%7}, {%8,%9}, {%0,%1,%2,%3};"
        : "+f"(d[0]), "+f"(d[1]), "+f"(d[2]), "+f"(d[3])
        : "r"(a[0]), "r"(a[1]), "r"(a[2]), "r"(a[3]), "r"(b[0]), "r"(b[1]));
}

__global__ __launch_bounds__(256, 2) void k_logits_mma(const float* __restrict__ enc,
                                                       const float* __restrict__ Wf) {
    extern __shared__ char dsm[];
    __shared__ float s_c[128], s_w[128];
    __shared__ float ep[4][128];

    const int tid    = threadIdx.x;
    const int nb     = blockIdx.x;               // 0..3
    const int m_base = blockIdx.y * 128;
    const int n_base = nb * 128;
    const int b      = m_base / L_;

    const int wid    = tid >> 5;
    const int lane   = tid & 31;
    const int g      = lane >> 2;                // 0..7
    const int t4     = lane & 3;                 // 0..3
    const int warp_m = wid >> 2;                 // 0..1
    const int warp_n = wid & 3;                  // 0..3
    const int m0     = warp_m * 64;
    const int n0     = warp_n * 32;

    if (tid < 128) {
        s_c[tid] = g_att2[b * ATT_ + n_base + tid];
        s_w[tid] = Wf[n_base + tid];
    }

    const uint32_t smem = smem_u32(dsm);

    // ---- stage loader: 2048 16B chunks, 8 per thread ----
    auto load_stage = [&](int st, int k0f) {
        const uint32_t sb = smem + st * STG;
        #pragma unroll
        for (int it = 0; it < 8; it++) {
            int t = tid + it * 256;
            if (t < 1024) {
                int row = t >> 3, c = t & 7;
                const float* src = enc + (size_t)(m_base + row) * ENC_ + k0f + c * 4;
                CP_ASYNC16(sb + row * 128 + ((c ^ (row & 7)) << 4), src);
            } else {
                int u = t - 1024;
                int n = u >> 3, c = u & 7;
                const float* src = g_Wt + (size_t)(n_base + n) * ENC_ + k0f + c * 4;
                CP_ASYNC16(sb + A_STG + n * 128 + ((c ^ (n & 7)) << 4), src);
            }
        }
        asm volatile("cp.async.commit_group;" ::: "memory");
    };

    float acc[4][4][4];
    #pragma unroll
    for (int mi = 0; mi < 4; mi++)
        #pragma unroll
        for (int ni = 0; ni < 4; ni++)
            #pragma unroll
            for (int j = 0; j < 4; j++) acc[mi][ni][j] = 0.f;

    load_stage(0, 0);
    load_stage(1, BK);

    int stage = 0;
    for (int i = 0; i < NITER; i++) {
        if (i + 1 < NITER)
            asm volatile("cp.async.wait_group 1;" ::: "memory");
        else
            asm volatile("cp.async.wait_group 0;" ::: "memory");
        __syncthreads();   // stage `i` ready; also: all readers of stage (i+2)%3 done

        if (i + 2 < NITER) {
            int nxt = stage + 2;
            if (nxt >= NSTAGE) nxt -= NSTAGE;
            load_stage(nxt, (i + 2) * BK);
        }

        const uint32_t sb = smem + stage * STG;
        const uint32_t Aoff = (uint32_t)(sb - smem) + t4 * 4;
        const uint32_t Boff = (uint32_t)(sb - smem) + A_STG + t4 * 4;

        #pragma unroll
        for (int s = 0; s < 4; s++) {
            const uint32_t x0 = (uint32_t)((2 * s) ^ g) << 4;
            const uint32_t x1 = (uint32_t)((2 * s + 1) ^ g) << 4;

            uint32_t af[4][4], bf[4][2];
            #pragma unroll
            for (int mi = 0; mi < 4; mi++) {
                uint32_t r = Aoff + (uint32_t)(m0 + mi * 16 + g) * 128;
                af[mi][0] = *(const uint32_t*)(dsm + r + x0);
                af[mi][1] = *(const uint32_t*)(dsm + r + 1024 + x0);
                af[mi][2] = *(const uint32_t*)(dsm + r + x1);
                af[mi][3] = *(const uint32_t*)(dsm + r + 1024 + x1);
            }
            #pragma unroll
            for (int ni = 0; ni < 4; ni++) {
                uint32_t r = Boff + (uint32_t)(n0 + ni * 8 + g) * 128;
                bf[ni][0] = *(const uint32_t*)(dsm + r + x0);
                bf[ni][1] = *(const uint32_t*)(dsm + r + x1);
            }
            #pragma unroll
            for (int mi = 0; mi < 4; mi++)
                #pragma unroll
                for (int ni = 0; ni < 4; ni++)
                    mma_tf32(acc[mi][ni], af[mi], bf[ni]);
        }

        stage++;
        if (stage == NSTAGE) stage = 0;
    }

    // ---- epilogue: relu(acc + att2)·Wf, reduce over this CTA's 128 cols ----
    #pragma unroll
    for (int mi = 0; mi < 4; mi++) {
        float r0s = 0.f, r1s = 0.f;
        #pragma unroll
        for (int ni = 0; ni < 4; ni++) {
            int c = n0 + ni * 8 + 2 * t4;
            float v;
            v = acc[mi][ni][0] + s_c[c];     v = fmaxf(v, 0.f); r0s = fmaf(v, s_w[c], r0s);
            v = acc[mi][ni][1] + s_c[c + 1]; v = fmaxf(v, 0.f); r0s = fmaf(v, s_w[c + 1], r0s);
            v = acc[mi][ni][2] + s_c[c];     v = fmaxf(v, 0.f); r1s = fmaf(v, s_w[c], r1s);
            v = acc[mi][ni][3] + s_c[c + 1]; v = fmaxf(v, 0.f); r1s = fmaf(v, s_w[c + 1], r1s);
        }
        r0s += __shfl_xor_sync(0xffffffffu, r0s, 1);
        r0s += __shfl_xor_sync(0xffffffffu, r0s, 2);
        r1s += __shfl_xor_sync(0xffffffffu, r1s, 1);
        r1s += __shfl_xor_sync(0xffffffffu, r1s, 2);
        if (t4 == 0) {
            ep[warp_n][m0 + mi * 16 + g]     = r0s;
            ep[warp_n][m0 + mi * 16 + 8 + g] = r1s;
        }
    }
    __syncthreads();
    if (tid < 128) {
        float lg = ep[0][tid] + ep[1][tid] + ep[2][tid] + ep[3][tid];
        g_part[nb * (B_ * L_) + m_base + tid] = lg;
    }
}

// ============================================================
// softmax over L per batch (sums the 4 N-partials)
// ============================================================
__global__ void k_softmax(float* __restrict__ out_att) {
    const int b = blockIdx.x, tid = threadIdx.x;
    __shared__ float red[8];
    float v[4];
    #pragma unroll
    for (int i = 0; i < 4; i++) {
        int l = tid + i * 256;
        float s = 0.f;
        #pragma unroll
        for (int p = 0; p < 4; p++) s += g_part[p * (B_ * L_) + b * L_ + l];
        v[i] = s;
    }
    float mx = fmaxf(fmaxf(v[0], v[1]), fmaxf(v[2], v[3]));
    #pragma unroll
    for (int off = 16; off; off >>= 1) mx = fmaxf(mx, __shfl_xor_sync(0xffffffffu, mx, off));
    if ((tid & 31) == 0) red[tid >> 5] = mx;
    __syncthreads();
    float bm = red[0];
    #pragma unroll
    for (int i = 1; i < 8; i++) bm = fmaxf(bm, red[i]);
    __syncthreads();
    float sum = 0.f;
    #pragma unroll
    for (int i = 0; i < 4; i++) { v[i] = expf(v[i] - bm); sum += v[i]; }
    #pragma unroll
    for (int off = 16; off; off >>= 1) sum += __shfl_xor_sync(0xffffffffu, sum, off);
    if ((tid & 31) == 0) red[tid >> 5] = sum;
    __syncthreads();
    float tot = 0.f;
    #pragma unroll
    for (int i = 0; i < 8; i++) tot += red[i];
    float inv = 1.f / tot;
    #pragma unroll
    for (int i = 0; i < 4; i++) out_att[b * L_ + tid + i * 256] = v[i] * inv;
}

// ============================================================
// context partials: full-row streaming, 2 float4 per thread
// grid(4, B_), block(256)
// ============================================================
__global__ __launch_bounds__(256) void k_context(const float* __restrict__ enc,
                                                 const float* __restrict__ att) {
    const int z = blockIdx.x, b = blockIdx.y, tid = threadIdx.x;
    __shared__ float sa[256];
    sa[tid] = att[b * L_ + z * 256 + tid];
    __syncthreads();

    const float4* base = (const float4*)(enc + (size_t)b * L_ * ENC_ + (size_t)z * 256 * ENC_);
    float4 a0 = make_float4(0.f, 0.f, 0.f, 0.f);
    float4 a1 = make_float4(0.f, 0.f, 0.f, 0.f);
    #pragma unroll 8
    for (int l = 0; l < 256; l++) {
        const float4* row = base + (size_t)l * (ENC_ / 4);
        float4 x0 = row[tid];
        float4 x1 = row[tid + 256];
        float w = sa[l];
        a0.x = fmaf(w, x0.x, a0.x); a0.y = fmaf(w, x0.y, a0.y);
        a0.z = fmaf(w, x0.z, a0.z); a0.w = fmaf(w, x0.w, a0.w);
        a1.x = fmaf(w, x1.x, a1.x); a1.y = fmaf(w, x1.y, a1.y);
        a1.z = fmaf(w, x1.z, a1.z); a1.w = fmaf(w, x1.w, a1.w);
    }
    float4* dst = (float4*)(g_ctxp + (size_t)z * B_ * ENC_ + (size_t)b * ENC_);
    dst[tid]       = a0;
    dst[tid + 256] = a1;
}

__global__ void k_ctx_reduce(float* __restrict__ ctx) {
    int i = blockIdx.x * 256 + threadIdx.x;
    float s = 0.f;
    #pragma unroll
    for (int z = 0; z < 4; z++) s += g_ctxp[z * (B_ * ENC_) + i];
    ctx[i] = s;
}

// ============================================================
extern "C" void kernel_launch(void* const* d_in, const int* in_sizes, int n_in,
                              void* d_out, int out_size) {
    const float* enc  = (const float*)d_in[0];
    const float* dech = (const float*)d_in[1];
    const float* We   = (const float*)d_in[2];
    const float* be   = (const float*)d_in[3];
    const float* Wd   = (const float*)d_in[4];
    const float* bd   = (const float*)d_in[5];
    const float* Wf   = (const float*)d_in[6];
    // d_in[7] = b_full: constant logit shift, invariant under softmax -> unused

    float* out_ctx = (float*)d_out;
    float* out_att = (float*)d_out + B_ * ENC_;

    static int smem_set = 0;
    if (!smem_set) {
        cudaFuncSetAttribute(k_logits_mma, cudaFuncAttributeMaxDynamicSharedMemorySize, SMEM_DYN);
        smem_set = 1;
    }

    dim3 gt(ENC_ / 32, ATT_ / 32);
    k_transpose<<<gt, dim3(32, 8)>>>(We);
    k_att2<<<B_, 512>>>(dech, Wd, bd, be);
    dim3 g2(4, B_ * L_ / 128);                   // (4, 512)
    k_logits_mma<<<g2, 256, SMEM_DYN>>>(enc, Wf);
    k_softmax<<<B_, 256>>>(out_att);
    dim3 g4(4, B_);
    k_context<<<g4, 256>>>(enc, out_att);
    k_ctx_reduce<<<B_ * ENC_ / 256, 256>>>(out_ctx);
}

// round 5
// speedup vs baseline: 1.0234x; 1.0234x over previous
#include <cuda_runtime.h>
#include <cstdint>

#define B_   64
#define L_   1024
#define ENC_ 2048
#define DEC_ 512
#define ATT_ 512

// ---------------- scratch (no allocs allowed) ----------------
__device__ float g_att2[B_ * ATT_];            // att2 + b_enc + b_dec
__device__ float g_part[4 * B_ * L_];          // logit partials per N-chunk
__device__ float g_Wt[ATT_ * ENC_];            // W_enc^T (ATT, ENC), tf32-rounded
__device__ float g_ctxp[4 * B_ * ENC_];        // context partials (L-split)
__device__ float g_sink[1];                    // dummy-kernel target

// ============================================================
// Dummy: pads launch order so the GEMM lands at launch idx 3
// (the index ncu's skip-count captures).
// ============================================================
__global__ void k_dummy() { g_sink[0] = 0.f; }

// ============================================================
// Transpose W_enc (ENC,ATT) -> g_Wt (ATT,ENC), rounding to tf32 (rna)
// ============================================================
__global__ void k_transpose(const float* __restrict__ We) {
    __shared__ float t[32][33];
    const int k0 = blockIdx.x * 32, n0 = blockIdx.y * 32;
    const int tx = threadIdx.x, ty = threadIdx.y;  // (32, 8)
    #pragma unroll
    for (int j = 0; j < 4; j++) {
        float v = We[(size_t)(k0 + ty + j * 8) * ATT_ + n0 + tx];
        uint32_t r;
        asm("cvt.rna.tf32.f32 %0, %1;" : "=r"(r) : "f"(v));
        t[ty + j * 8][tx] = __uint_as_float(r);
    }
    __syncthreads();
    #pragma unroll
    for (int j = 0; j < 4; j++)
        g_Wt[(size_t)(n0 + ty + j * 8) * ENC_ + k0 + tx] = t[tx][ty + j * 8];
}

// ============================================================
// att2[b][a] = dec[b]·W_dec[:,a] + b_dec[a] + b_enc[a]
// ============================================================
__global__ void k_att2(const float* __restrict__ dec, const float* __restrict__ Wd,
                       const float* __restrict__ bd, const float* __restrict__ be) {
    __shared__ float s[DEC_];
    int b = blockIdx.x, a = threadIdx.x;
    for (int d = threadIdx.x; d < DEC_; d += blockDim.x) s[d] = dec[b * DEC_ + d];
    __syncthreads();
    float acc = bd[a] + be[a];
    #pragma unroll 8
    for (int d = 0; d < DEC_; d++) acc = fmaf(s[d], Wd[d * ATT_ + a], acc);
    g_att2[b * ATT_ + a] = acc;
}

// ============================================================
// Big GEMM via mma.sync tf32 + fused relu/dot epilogue
// CTA 128x128, BK=32, 3-stage cp.async ring, one sync per iter.
// 4 warps (128 thr), warp tile 64x64 (2x2). Natural occ 2.
// grid(4, 512), block(128)
// ============================================================
#define BK       32
#define NITER    (ENC_ / BK)            // 64
#define A_STG    16384                  // 128 rows * 128B
#define B_STG    16384
#define STG      (A_STG + B_STG)        // 32768
#define NSTAGE   3
#define SMEM_DYN (NSTAGE * STG)         // 98304

#define CP_ASYNC16(dst, src) \
    asm volatile("cp.async.cg.shared.global [%0], [%1], 16;" :: "r"(dst), "l"(src) : "memory")

__device__ __forceinline__ uint32_t smem_u32(const void* p) {
    uint32_t a;
    asm("{ .reg .u64 t; cvta.to.shared.u64 t, %1; cvt.u32.u64 %0, t; }" : "=r"(a) : "l"(p));
    return a;
}

__device__ __forceinline__ void mma_tf32(float* d, const uint32_t* a, const uint32_t* b) {
    asm volatile(
        "mma.sync.aligned.m16n8k8.row.col.f32.tf32.tf32.f32 "
        "{%0,%1,%2,%3}, {%4,%5,%6,%7}, {%8,%9}, {%0,%1,%2,%3};"
        : "+f"(d[0]), "+f"(d[1]), "+f"(d[2]), "+f"(d[3])
        : "r"(a[0]), "r"(a[1]), "r"(a[2]), "r"(a[3]), "r"(b[0]), "r"(b[1]));
}

__global__ __launch_bounds__(128) void k_logits_mma(const float* __restrict__ enc,
                                                    const float* __restrict__ Wf) {
    extern __shared__ char dsm[];
    __shared__ float s_c[128], s_w[128];
    __shared__ float ep[2][128];

    const int tid    = threadIdx.x;
    const int nb     = blockIdx.x;               // 0..3
    const int m_base = blockIdx.y * 128;
    const int n_base = nb * 128;
    const int b      = m_base / L_;

    const int wid    = tid >> 5;
    const int lane   = tid & 31;
    const int g      = lane >> 2;                // 0..7
    const int t4     = lane & 3;                 // 0..3
    const int warp_m = wid >> 1;                 // 0..1
    const int warp_n = wid & 1;                  // 0..1
    const int m0     = warp_m * 64;
    const int n0     = warp_n * 64;

    s_c[tid] = g_att2[b * ATT_ + n_base + tid];
    s_w[tid] = Wf[n_base + tid];

    const uint32_t smem = smem_u32(dsm);

    // ---- stage loader: 2048 16B chunks, 16 per thread ----
    auto load_stage = [&](int st, int k0f) {
        const uint32_t sb = smem + st * STG;
        #pragma unroll
        for (int it = 0; it < 16; it++) {
            int t = tid + it * 128;
            if (t < 1024) {
                int row = t >> 3, c = t & 7;
                const float* src = enc + (size_t)(m_base + row) * ENC_ + k0f + c * 4;
                CP_ASYNC16(sb + row * 128 + ((c ^ (row & 7)) << 4), src);
            } else {
                int u = t - 1024;
                int n = u >> 3, c = u & 7;
                const float* src = g_Wt + (size_t)(n_base + n) * ENC_ + k0f + c * 4;
                CP_ASYNC16(sb + A_STG + n * 128 + ((c ^ (n & 7)) << 4), src);
            }
        }
        asm volatile("cp.async.commit_group;" ::: "memory");
    };

    float acc[4][8][4];
    #pragma unroll
    for (int mi = 0; mi < 4; mi++)
        #pragma unroll
        for (int ni = 0; ni < 8; ni++)
            #pragma unroll
            for (int j = 0; j < 4; j++) acc[mi][ni][j] = 0.f;

    load_stage(0, 0);
    load_stage(1, BK);

    int stage = 0;
    for (int i = 0; i < NITER; i++) {
        if (i + 1 < NITER)
            asm volatile("cp.async.wait_group 1;" ::: "memory");
        else
            asm volatile("cp.async.wait_group 0;" ::: "memory");
        __syncthreads();   // stage `i` ready; readers of stage (i+2)%3 are done

        if (i + 2 < NITER) {
            int nxt = stage + 2;
            if (nxt >= NSTAGE) nxt -= NSTAGE;
            load_stage(nxt, (i + 2) * BK);
        }

        const uint32_t off  = (uint32_t)stage * STG;
        const uint32_t Aoff = off + t4 * 4;
        const uint32_t Boff = off + A_STG + t4 * 4;

        #pragma unroll
        for (int s = 0; s < 4; s++) {
            const uint32_t x0 = (uint32_t)((2 * s) ^ g) << 4;
            const uint32_t x1 = (uint32_t)((2 * s + 1) ^ g) << 4;

            uint32_t af[4][4], bf[8][2];
            #pragma unroll
            for (int mi = 0; mi < 4; mi++) {
                uint32_t r = Aoff + (uint32_t)(m0 + mi * 16 + g) * 128;
                af[mi][0] = *(const uint32_t*)(dsm + r + x0);
                af[mi][1] = *(const uint32_t*)(dsm + r + 1024 + x0);
                af[mi][2] = *(const uint32_t*)(dsm + r + x1);
                af[mi][3] = *(const uint32_t*)(dsm + r + 1024 + x1);
            }
            #pragma unroll
            for (int ni = 0; ni < 8; ni++) {
                uint32_t r = Boff + (uint32_t)(n0 + ni * 8 + g) * 128;
                bf[ni][0] = *(const uint32_t*)(dsm + r + x0);
                bf[ni][1] = *(const uint32_t*)(dsm + r + x1);
            }
            #pragma unroll
            for (int mi = 0; mi < 4; mi++)
                #pragma unroll
                for (int ni = 0; ni < 8; ni++)
                    mma_tf32(acc[mi][ni], af[mi], bf[ni]);
        }

        stage++;
        if (stage == NSTAGE) stage = 0;
    }

    // ---- epilogue: relu(acc + att2)·Wf, reduce over 128 cols ----
    #pragma unroll
    for (int mi = 0; mi < 4; mi++) {
        float r0s = 0.f, r1s = 0.f;
        #pragma unroll
        for (int ni = 0; ni < 8; ni++) {
            int c = n0 + ni * 8 + 2 * t4;
            float v;
            v = acc[mi][ni][0] + s_c[c];     v = fmaxf(v, 0.f); r0s = fmaf(v, s_w[c], r0s);
            v = acc[mi][ni][1] + s_c[c + 1]; v = fmaxf(v, 0.f); r0s = fmaf(v, s_w[c + 1], r0s);
            v = acc[mi][ni][2] + s_c[c];     v = fmaxf(v, 0.f); r1s = fmaf(v, s_w[c], r1s);
            v = acc[mi][ni][3] + s_c[c + 1]; v = fmaxf(v, 0.f); r1s = fmaf(v, s_w[c + 1], r1s);
        }
        r0s += __shfl_xor_sync(0xffffffffu, r0s, 1);
        r0s += __shfl_xor_sync(0xffffffffu, r0s, 2);
        r1s += __shfl_xor_sync(0xffffffffu, r1s, 1);
        r1s += __shfl_xor_sync(0xffffffffu, r1s, 2);
        if (t4 == 0) {
            ep[warp_n][m0 + mi * 16 + g]     = r0s;
            ep[warp_n][m0 + mi * 16 + 8 + g] = r1s;
        }
    }
    __syncthreads();
    g_part[nb * (B_ * L_) + m_base + tid] = ep[0][tid] + ep[1][tid];
}

// ============================================================
// softmax over L per batch (sums the 4 N-partials)
// ============================================================
__global__ void k_softmax(float* __restrict__ out_att) {
    const int b = blockIdx.x, tid = threadIdx.x;
    __shared__ float red[8];
    float v[4];
    #pragma unroll
    for (int i = 0; i < 4; i++) {
        int l = tid + i * 256;
        float s = 0.f;
        #pragma unroll
        for (int p = 0; p < 4; p++) s += g_part[p * (B_ * L_) + b * L_ + l];
        v[i] = s;
    }
    float mx = fmaxf(fmaxf(v[0], v[1]), fmaxf(v[2], v[3]));
    #pragma unroll
    for (int off = 16; off; off >>= 1) mx = fmaxf(mx, __shfl_xor_sync(0xffffffffu, mx, off));
    if ((tid & 31) == 0) red[tid >> 5] = mx;
    __syncthreads();
    float bm = red[0];
    #pragma unroll
    for (int i = 1; i < 8; i++) bm = fmaxf(bm, red[i]);
    __syncthreads();
    float sum = 0.f;
    #pragma unroll
    for (int i = 0; i < 4; i++) { v[i] = expf(v[i] - bm); sum += v[i]; }
    #pragma unroll
    for (int off = 16; off; off >>= 1) sum += __shfl_xor_sync(0xffffffffu, sum, off);
    if ((tid & 31) == 0) red[tid >> 5] = sum;
    __syncthreads();
    float tot = 0.f;
    #pragma unroll
    for (int i = 0; i < 8; i++) tot += red[i];
    float inv = 1.f / tot;
    #pragma unroll
    for (int i = 0; i < 4; i++) out_att[b * L_ + tid + i * 256] = v[i] * inv;
}

// ============================================================
// context partials: full-row streaming, 2 float4 per thread
// grid(4, B_), block(256)
// ============================================================
__global__ __launch_bounds__(256) void k_context(const float* __restrict__ enc,
                                                 const float* __restrict__ att) {
    const int z = blockIdx.x, b = blockIdx.y, tid = threadIdx.x;
    __shared__ float sa[256];
    sa[tid] = att[b * L_ + z * 256 + tid];
    __syncthreads();

    const float4* base = (const float4*)(enc + (size_t)b * L_ * ENC_ + (size_t)z * 256 * ENC_);
    float4 a0 = make_float4(0.f, 0.f, 0.f, 0.f);
    float4 a1 = make_float4(0.f, 0.f, 0.f, 0.f);
    #pragma unroll 8
    for (int l = 0; l < 256; l++) {
        const float4* row = base + (size_t)l * (ENC_ / 4);
        float4 x0 = row[tid];
        float4 x1 = row[tid + 256];
        float w = sa[l];
        a0.x = fmaf(w, x0.x, a0.x); a0.y = fmaf(w, x0.y, a0.y);
        a0.z = fmaf(w, x0.z, a0.z); a0.w = fmaf(w, x0.w, a0.w);
        a1.x = fmaf(w, x1.x, a1.x); a1.y = fmaf(w, x1.y, a1.y);
        a1.z = fmaf(w, x1.z, a1.z); a1.w = fmaf(w, x1.w, a1.w);
    }
    float4* dst = (float4*)(g_ctxp + (size_t)z * B_ * ENC_ + (size_t)b * ENC_);
    dst[tid]       = a0;
    dst[tid + 256] = a1;
}

__global__ void k_ctx_reduce(float* __restrict__ ctx) {
    int i = blockIdx.x * 256 + threadIdx.x;
    float s = 0.f;
    #pragma unroll
    for (int z = 0; z < 4; z++) s += g_ctxp[z * (B_ * ENC_) + i];
    ctx[i] = s;
}

// ============================================================
extern "C" void kernel_launch(void* const* d_in, const int* in_sizes, int n_in,
                              void* d_out, int out_size) {
    const float* enc  = (const float*)d_in[0];
    const float* dech = (const float*)d_in[1];
    const float* We   = (const float*)d_in[2];
    const float* be   = (const float*)d_in[3];
    const float* Wd   = (const float*)d_in[4];
    const float* bd   = (const float*)d_in[5];
    const float* Wf   = (const float*)d_in[6];
    // d_in[7] = b_full: constant logit shift, invariant under softmax -> unused

    float* out_ctx = (float*)d_out;
    float* out_att = (float*)d_out + B_ * ENC_;

    static int smem_set = 0;
    if (!smem_set) {
        cudaFuncSetAttribute(k_logits_mma, cudaFuncAttributeMaxDynamicSharedMemorySize, SMEM_DYN);
        smem_set = 1;
    }

    dim3 gt(ENC_ / 32, ATT_ / 32);
    k_transpose<<<gt, dim3(32, 8)>>>(We);      // launch idx 0
    k_att2<<<B_, 512>>>(dech, Wd, bd, be);     // idx 1
    k_dummy<<<1, 1>>>();                        // idx 2 (pads GEMM to idx 3 for ncu)
    dim3 g2(4, B_ * L_ / 128);                  // (4, 512)
    k_logits_mma<<<g2, 128, SMEM_DYN>>>(enc, Wf);  // idx 3 <- profiled
    k_softmax<<<B_, 256>>>(out_att);
    dim3 g4(4, B_);
    k_context<<<g4, 256>>>(enc, out_att);
    k_ctx_reduce<<<B_ * ENC_ / 256, 256>>>(out_ctx);
}

// round 6
// speedup vs baseline: 1.1276x; 1.1019x over previous
#include <cuda_runtime.h>
#include <cstdint>

#define B_   64
#define L_   1024
#define ENC_ 2048
#define DEC_ 512
#define ATT_ 512

// ---------------- scratch (no allocs allowed) ----------------
__device__ float g_att2[B_ * ATT_];            // att2 + b_enc + b_dec
__device__ float g_part[4 * B_ * L_];          // logit partials per N-chunk
__device__ float g_Wt[ATT_ * ENC_];            // W_enc^T (ATT, ENC), tf32-rounded
__device__ float g_ctxp[4 * B_ * ENC_];        // context partials (L-split)
__device__ float g_sink[1];                    // dummy-kernel target

// ============================================================
// Dummy: pads launch order so the GEMM lands at ncu's idx 3
// ============================================================
__global__ void k_dummy() { g_sink[0] = 0.f; }

// ============================================================
// Transpose W_enc (ENC,ATT) -> g_Wt (ATT,ENC), rounding to tf32 (rna)
// ============================================================
__global__ void k_transpose(const float* __restrict__ We) {
    __shared__ float t[32][33];
    const int k0 = blockIdx.x * 32, n0 = blockIdx.y * 32;
    const int tx = threadIdx.x, ty = threadIdx.y;  // (32, 8)
    #pragma unroll
    for (int j = 0; j < 4; j++) {
        float v = We[(size_t)(k0 + ty + j * 8) * ATT_ + n0 + tx];
        uint32_t r;
        asm("cvt.rna.tf32.f32 %0, %1;" : "=r"(r) : "f"(v));
        t[ty + j * 8][tx] = __uint_as_float(r);
    }
    __syncthreads();
    #pragma unroll
    for (int j = 0; j < 4; j++)
        g_Wt[(size_t)(n0 + ty + j * 8) * ENC_ + k0 + tx] = t[tx][ty + j * 8];
}

// ============================================================
// att2[b][a] = dec[b]·W_dec[:,a] + b_dec[a] + b_enc[a]
// ============================================================
__global__ void k_att2(const float* __restrict__ dec, const float* __restrict__ Wd,
                       const float* __restrict__ bd, const float* __restrict__ be) {
    __shared__ float s[DEC_];
    int b = blockIdx.x, a = threadIdx.x;
    for (int d = threadIdx.x; d < DEC_; d += blockDim.x) s[d] = dec[b * DEC_ + d];
    __syncthreads();
    float acc = bd[a] + be[a];
    #pragma unroll 8
    for (int d = 0; d < DEC_; d++) acc = fmaf(s[d], Wd[d * ATT_ + a], acc);
    g_att2[b * ATT_ + a] = acc;
}

// ============================================================
// Big GEMM via mma.sync tf32, ldmatrix fragment feed,
// double-buffered s-steps, 3-stage cp.async ring, 1 sync/iter.
// CTA 128x128, 4 warps, warp tile 64x64. grid(4, 512), block(128)
// ============================================================
#define BK       32
#define NITER    (ENC_ / BK)            // 64
#define A_STG    16384                  // 128 rows * 128B
#define STG      32768
#define NSTAGE   3
#define SMEM_DYN (NSTAGE * STG)         // 98304

#define CP_ASYNC16(dst, src) \
    asm volatile("cp.async.cg.shared.global [%0], [%1], 16;" :: "r"(dst), "l"(src) : "memory")

#define LDSM4(r, a) \
    asm volatile("ldmatrix.sync.aligned.m8n8.x4.shared.b16 {%0,%1,%2,%3}, [%4];" \
        : "=r"((r)[0]), "=r"((r)[1]), "=r"((r)[2]), "=r"((r)[3]) : "r"(a))

__device__ __forceinline__ uint32_t smem_u32(const void* p) {
    uint32_t a;
    asm("{ .reg .u64 t; cvta.to.shared.u64 t, %1; cvt.u32.u64 %0, t; }" : "=r"(a) : "l"(p));
    return a;
}

__device__ __forceinline__ void mma_tf32(float* d, const uint32_t* a, const uint32_t* b) {
    asm volatile(
        "mma.sync.aligned.m16n8k8.row.col.f32.tf32.tf32.f32 "
        "{%0,%1,%2,%3}, {%4,%5,%6,%7}, {%8,%9}, {%0,%1,%2,%3};"
        : "+f"(d[0]), "+f"(d[1]), "+f"(d[2]), "+f"(d[3])
        : "r"(a[0]), "r"(a[1]), "r"(a[2]), "r"(a[3]), "r"(b[0]), "r"(b[1]));
}

__global__ __launch_bounds__(128) void k_logits_mma(const float* __restrict__ enc,
                                                    const float* __restrict__ Wf) {
    extern __shared__ char dsm[];
    __shared__ float s_c[128], s_w[128];
    __shared__ float ep[2][128];

    const int tid    = threadIdx.x;
    const int nb     = blockIdx.x;               // 0..3
    const int m_base = blockIdx.y * 128;
    const int n_base = nb * 128;
    const int b      = m_base / L_;

    const int wid    = tid >> 5;
    const int lane   = tid & 31;
    const int g      = lane >> 2;
    const int t4     = lane & 3;
    const int warp_m = wid >> 1;                 // 0..1
    const int warp_n = wid & 1;                  // 0..1
    const int m0     = warp_m * 64;
    const int n0     = warp_n * 64;

    // per-lane ldmatrix row/chunk geometry
    const int hcA = lane >> 4;                   // chunk-half for A tiles
    const int rA  = m0 + (lane & 15);            // A smem row (+16*mi)
    const int rA7 = rA & 7;
    const int rB  = n0 + ((lane >> 4) << 3) + (lane & 7);  // B smem row (+16*j)
    const int hcB = (lane >> 3) & 1;             // chunk-half for B tiles
    const int rB7 = rB & 7;

    s_c[tid] = g_att2[b * ATT_ + n_base + tid];
    s_w[tid] = Wf[n_base + tid];

    const uint32_t smem = smem_u32(dsm);

    // ---- stage loader: 2048 16B chunks, 16 per thread ----
    auto load_stage = [&](int st, int k0f) {
        const uint32_t sb = smem + st * STG;
        #pragma unroll
        for (int it = 0; it < 16; it++) {
            int t = tid + it * 128;
            if (t < 1024) {
                int row = t >> 3, c = t & 7;
                const float* src = enc + (size_t)(m_base + row) * ENC_ + k0f + c * 4;
                CP_ASYNC16(sb + row * 128 + ((c ^ (row & 7)) << 4), src);
            } else {
                int u = t - 1024;
                int n = u >> 3, c = u & 7;
                const float* src = g_Wt + (size_t)(n_base + n) * ENC_ + k0f + c * 4;
                CP_ASYNC16(sb + A_STG + n * 128 + ((c ^ (n & 7)) << 4), src);
            }
        }
        asm volatile("cp.async.commit_group;" ::: "memory");
    };

    float acc[4][8][4];
    #pragma unroll
    for (int mi = 0; mi < 4; mi++)
        #pragma unroll
        for (int ni = 0; ni < 8; ni++)
            #pragma unroll
            for (int j = 0; j < 4; j++) acc[mi][ni][j] = 0.f;

    uint32_t aF[2][4][4], bF[2][4][4];   // bF[buf][j]: regs {b[2j][0], b[2j][1], b[2j+1][0], b[2j+1][1]}

    load_stage(0, 0);
    load_stage(1, BK);

    int stage = 0;
    for (int i = 0; i < NITER; i++) {
        if (i + 1 < NITER)
            asm volatile("cp.async.wait_group 1;" ::: "memory");
        else
            asm volatile("cp.async.wait_group 0;" ::: "memory");
        __syncthreads();   // stage `i` ready; readers of stage (i+2)%3 done

        if (i + 2 < NITER) {
            int nxt = stage + 2;
            if (nxt >= NSTAGE) nxt -= NSTAGE;
            load_stage(nxt, (i + 2) * BK);
        }

        const uint32_t off = smem + (uint32_t)stage * STG;

        // frag prefetch for s-step `s` into buffer `buf`
        auto load_frags = [&](int buf, int s) {
            const uint32_t ca = (uint32_t)(((2 * s + hcA) ^ rA7)) << 4;
            #pragma unroll
            for (int mi = 0; mi < 4; mi++)
                LDSM4(aF[buf][mi], off + (uint32_t)(rA + 16 * mi) * 128 + ca);
            const uint32_t cb = (uint32_t)(((2 * s + hcB) ^ rB7)) << 4;
            #pragma unroll
            for (int j = 0; j < 4; j++)
                LDSM4(bF[buf][j], off + A_STG + (uint32_t)(rB + 16 * j) * 128 + cb);
        };

        load_frags(0, 0);
        #pragma unroll
        for (int s = 0; s < 4; s++) {
            if (s < 3) load_frags((s + 1) & 1, s + 1);
            const int cb = s & 1;
            #pragma unroll
            for (int mi = 0; mi < 4; mi++)
                #pragma unroll
                for (int j = 0; j < 4; j++) {
                    mma_tf32(acc[mi][2 * j],     aF[cb][mi], &bF[cb][j][0]);
                    mma_tf32(acc[mi][2 * j + 1], aF[cb][mi], &bF[cb][j][2]);
                }
        }

        stage++;
        if (stage == NSTAGE) stage = 0;
    }

    // ---- epilogue: relu(acc + att2)·Wf, reduce over 128 cols ----
    #pragma unroll
    for (int mi = 0; mi < 4; mi++) {
        float r0s = 0.f, r1s = 0.f;
        #pragma unroll
        for (int ni = 0; ni < 8; ni++) {
            int c = n0 + ni * 8 + 2 * t4;
            float v;
            v = acc[mi][ni][0] + s_c[c];     v = fmaxf(v, 0.f); r0s = fmaf(v, s_w[c], r0s);
            v = acc[mi][ni][1] + s_c[c + 1]; v = fmaxf(v, 0.f); r0s = fmaf(v, s_w[c + 1], r0s);
            v = acc[mi][ni][2] + s_c[c];     v = fmaxf(v, 0.f); r1s = fmaf(v, s_w[c], r1s);
            v = acc[mi][ni][3] + s_c[c + 1]; v = fmaxf(v, 0.f); r1s = fmaf(v, s_w[c + 1], r1s);
        }
        r0s += __shfl_xor_sync(0xffffffffu, r0s, 1);
        r0s += __shfl_xor_sync(0xffffffffu, r0s, 2);
        r1s += __shfl_xor_sync(0xffffffffu, r1s, 1);
        r1s += __shfl_xor_sync(0xffffffffu, r1s, 2);
        if (t4 == 0) {
            ep[warp_n][m0 + mi * 16 + g]     = r0s;
            ep[warp_n][m0 + mi * 16 + 8 + g] = r1s;
        }
    }
    __syncthreads();
    g_part[nb * (B_ * L_) + m_base + tid] = ep[0][tid] + ep[1][tid];
}

// ============================================================
// softmax over L per batch (sums the 4 N-partials)
// ============================================================
__global__ void k_softmax(float* __restrict__ out_att) {
    const int b = blockIdx.x, tid = threadIdx.x;
    __shared__ float red[8];
    float v[4];
    #pragma unroll
    for (int i = 0; i < 4; i++) {
        int l = tid + i * 256;
        float s = 0.f;
        #pragma unroll
        for (int p = 0; p < 4; p++) s += g_part[p * (B_ * L_) + b * L_ + l];
        v[i] = s;
    }
    float mx = fmaxf(fmaxf(v[0], v[1]), fmaxf(v[2], v[3]));
    #pragma unroll
    for (int off = 16; off; off >>= 1) mx = fmaxf(mx, __shfl_xor_sync(0xffffffffu, mx, off));
    if ((tid & 31) == 0) red[tid >> 5] = mx;
    __syncthreads();
    float bm = red[0];
    #pragma unroll
    for (int i = 1; i < 8; i++) bm = fmaxf(bm, red[i]);
    __syncthreads();
    float sum = 0.f;
    #pragma unroll
    for (int i = 0; i < 4; i++) { v[i] = expf(v[i] - bm); sum += v[i]; }
    #pragma unroll
    for (int off = 16; off; off >>= 1) sum += __shfl_xor_sync(0xffffffffu, sum, off);
    if ((tid & 31) == 0) red[tid >> 5] = sum;
    __syncthreads();
    float tot = 0.f;
    #pragma unroll
    for (int i = 0; i < 8; i++) tot += red[i];
    float inv = 1.f / tot;
    #pragma unroll
    for (int i = 0; i < 4; i++) out_att[b * L_ + tid + i * 256] = v[i] * inv;
}

// ============================================================
// context partials: full-row streaming, 2 float4 per thread
// grid(4, B_), block(256)
// ============================================================
__global__ __launch_bounds__(256) void k_context(const float* __restrict__ enc,
                                                 const float* __restrict__ att) {
    const int z = blockIdx.x, b = blockIdx.y, tid = threadIdx.x;
    __shared__ float sa[256];
    sa[tid] = att[b * L_ + z * 256 + tid];
    __syncthreads();

    const float4* base = (const float4*)(enc + (size_t)b * L_ * ENC_ + (size_t)z * 256 * ENC_);
    float4 a0 = make_float4(0.f, 0.f, 0.f, 0.f);
    float4 a1 = make_float4(0.f, 0.f, 0.f, 0.f);
    #pragma unroll 8
    for (int l = 0; l < 256; l++) {
        const float4* row = base + (size_t)l * (ENC_ / 4);
        float4 x0 = row[tid];
        float4 x1 = row[tid + 256];
        float w = sa[l];
        a0.x = fmaf(w, x0.x, a0.x); a0.y = fmaf(w, x0.y, a0.y);
        a0.z = fmaf(w, x0.z, a0.z); a0.w = fmaf(w, x0.w, a0.w);
        a1.x = fmaf(w, x1.x, a1.x); a1.y = fmaf(w, x1.y, a1.y);
        a1.z = fmaf(w, x1.z, a1.z); a1.w = fmaf(w, x1.w, a1.w);
    }
    float4* dst = (float4*)(g_ctxp + (size_t)z * B_ * ENC_ + (size_t)b * ENC_);
    dst[tid]       = a0;
    dst[tid + 256] = a1;
}

__global__ void k_ctx_reduce(float* __restrict__ ctx) {
    int i = blockIdx.x * 256 + threadIdx.x;
    float s = 0.f;
    #pragma unroll
    for (int z = 0; z < 4; z++) s += g_ctxp[z * (B_ * ENC_) + i];
    ctx[i] = s;
}

// ============================================================
extern "C" void kernel_launch(void* const* d_in, const int* in_sizes, int n_in,
                              void* d_out, int out_size) {
    const float* enc  = (const float*)d_in[0];
    const float* dech = (const float*)d_in[1];
    const float* We   = (const float*)d_in[2];
    const float* be   = (const float*)d_in[3];
    const float* Wd   = (const float*)d_in[4];
    const float* bd   = (const float*)d_in[5];
    const float* Wf   = (const float*)d_in[6];
    // d_in[7] = b_full: constant logit shift, invariant under softmax -> unused

    float* out_ctx = (float*)d_out;
    float* out_att = (float*)d_out + B_ * ENC_;

    static int smem_set = 0;
    if (!smem_set) {
        cudaFuncSetAttribute(k_logits_mma, cudaFuncAttributeMaxDynamicSharedMemorySize, SMEM_DYN);
        smem_set = 1;
    }

    dim3 gt(ENC_ / 32, ATT_ / 32);
    k_transpose<<<gt, dim3(32, 8)>>>(We);      // idx 0
    k_att2<<<B_, 512>>>(dech, Wd, bd, be);     // idx 1
    k_dummy<<<1, 1>>>();                        // idx 2
    dim3 g2(4, B_ * L_ / 128);                  // (4, 512)
    k_logits_mma<<<g2, 128, SMEM_DYN>>>(enc, Wf);  // idx 3 <- profiled
    k_softmax<<<B_, 256>>>(out_att);
    dim3 g4(4, B_);
    k_context<<<g4, 256>>>(enc, out_att);
    k_ctx_reduce<<<B_ * ENC_ / 256, 256>>>(out_ctx);
}